// round 16
// baseline (speedup 1.0000x reference)
#include <cuda_runtime.h>
#include <cstdint>

#define BB 96
#define HH 100
#define NN 128
#define DD 768
#define AA 256
#define LDH (HH * DD)
#define PS  (BB * DD)        // 73728
#define PSQ (BB * AA)        // 24576
#define GRID 144
#define TPB 512
#define NBAR 11

// ---------------- scratch ----------------
__device__ float g_neigh[PS];
__device__ float g_bias [PS];
__device__ float g_u    [PS];
__device__ float g_Qv   [PSQ];
__device__ float g_P    [PS];
__device__ float g_R    [PS];
__device__ float g_hbar [PS];
__device__ float g_pB[12 * PS];
__device__ float g_pU[12 * PS];
__device__ float g_pQ[24 * PSQ];
__device__ float g_pP[8 * PS];
__device__ float g_pR[12 * PS];
__device__ float g_pO[12 * PS];
__device__ unsigned g_cnt  = 0;
__device__ unsigned g_rel  = 0;
__device__ unsigned g_base = 0;

// ---------------- f32x2 helpers ----------------
typedef unsigned long long ull;
__device__ __forceinline__ ull pk2(float x) {
    ull r; asm("mov.b64 %0, {%1, %1};" : "=l"(r) : "f"(x)); return r;
}
__device__ __forceinline__ void ffma2(ull& d, ull a, ull b) {
    asm("fma.rn.f32x2 %0, %1, %2, %0;" : "+l"(d) : "l"(a), "l"(b));
}
__device__ __forceinline__ float2 up2(ull v) {
    float2 r; asm("mov.b64 {%0, %1}, %2;" : "=f"(r.x), "=f"(r.y) : "l"(v)); return r;
}

// ---------------- global barrier (monotone counter) ----------------
__device__ __forceinline__ void gbar(unsigned target, int adv) {
    __syncthreads();
    if (threadIdx.x == 0) {
        __threadfence();
        unsigned a = atomicAdd(&g_cnt, 1u) + 1u;
        if (a == target) {
            if (adv) atomicExch(&g_base, target);
            atomicExch(&g_rel, target);
        } else {
            unsigned v;
            do {
                asm volatile("ld.volatile.global.u32 %0, [%1];" : "=r"(v) : "l"(&g_rel));
            } while ((int)(v - target) < 0);
        }
        __threadfence();
    }
    __syncthreads();
}

// ======== GEMM jobs: 512 threads, thread tile 6m x 4n, f32x2 core ====
// As layout [k][96] stride 98; Bs layout [k][128] stride 132.
__device__ __noinline__ void job_gemmT(const float* A, int lda, const float* B,
                                       int Kdim, int Nval, int nt, int k0, int nch,
                                       float* po, float* As, float* Bs) {
    const int tid = threadIdx.x;
    ull acc[6][2];
#pragma unroll
    for (int i = 0; i < 6; ++i) { acc[i][0] = 0ULL; acc[i][1] = 0ULL; }
    for (int c = 0; c < nch; ++c) {
        int kb = k0 + c * 32;
        float2 va[3], vb[4];
#pragma unroll
        for (int j = 0; j < 3; ++j) {
            int idx = tid + 512 * j; int m = idx >> 4, cc = idx & 15;
            va[j] = *(const float2*)(A + (size_t)m * lda + kb + 2 * cc);
        }
#pragma unroll
        for (int j = 0; j < 4; ++j) {
            int idx = tid + 512 * j; int n = idx >> 4, cc = idx & 15;
            vb[j] = *(const float2*)(B + (size_t)(nt * 128 + n) * Kdim + kb + 2 * cc);
        }
        __syncthreads();
#pragma unroll
        for (int j = 0; j < 3; ++j) {
            int idx = tid + 512 * j; int m = idx >> 4, cc = idx & 15;
            As[(2 * cc) * 98 + m] = va[j].x; As[(2 * cc + 1) * 98 + m] = va[j].y;
        }
#pragma unroll
        for (int j = 0; j < 4; ++j) {
            int idx = tid + 512 * j; int n = idx >> 4, cc = idx & 15;
            Bs[(2 * cc) * 132 + n] = vb[j].x; Bs[(2 * cc + 1) * 132 + n] = vb[j].y;
        }
        __syncthreads();
        const int mI = tid >> 5, nI = tid & 31;
#pragma unroll
        for (int k = 0; k < 32; ++k) {
            float2 a01 = *(const float2*)&As[k * 98 + 6 * mI];
            float2 a23 = *(const float2*)&As[k * 98 + 6 * mI + 2];
            float2 a45 = *(const float2*)&As[k * 98 + 6 * mI + 4];
            ulonglong2 bb = *(const ulonglong2*)&Bs[k * 132 + 4 * nI];
            ull ap0 = pk2(a01.x), ap1 = pk2(a01.y), ap2 = pk2(a23.x);
            ull ap3 = pk2(a23.y), ap4 = pk2(a45.x), ap5 = pk2(a45.y);
            ffma2(acc[0][0], ap0, bb.x); ffma2(acc[0][1], ap0, bb.y);
            ffma2(acc[1][0], ap1, bb.x); ffma2(acc[1][1], ap1, bb.y);
            ffma2(acc[2][0], ap2, bb.x); ffma2(acc[2][1], ap2, bb.y);
            ffma2(acc[3][0], ap3, bb.x); ffma2(acc[3][1], ap3, bb.y);
            ffma2(acc[4][0], ap4, bb.x); ffma2(acc[4][1], ap4, bb.y);
            ffma2(acc[5][0], ap5, bb.x); ffma2(acc[5][1], ap5, bb.y);
        }
    }
    const int mI = tid >> 5, nI = tid & 31;
#pragma unroll
    for (int i = 0; i < 6; ++i) {
        int m = 6 * mI + i;
        float2 lo = up2(acc[i][0]), hi = up2(acc[i][1]);
        float4 v = make_float4(lo.x, lo.y, hi.x, hi.y);
        *(float4*)&po[(size_t)m * Nval + 4 * nI] = v;
    }
}

__device__ __noinline__ void job_gemmNT(const float* A, int lda, const float* B,
                                        int ldb, int Nval, int nt, int k0, int nch,
                                        float* po, float* As, float* Bs) {
    const int tid = threadIdx.x;
    ull acc[6][2];
#pragma unroll
    for (int i = 0; i < 6; ++i) { acc[i][0] = 0ULL; acc[i][1] = 0ULL; }
    for (int c = 0; c < nch; ++c) {
        int kb = k0 + c * 32;
        float2 va[3]; float4 wb[2];
#pragma unroll
        for (int j = 0; j < 3; ++j) {
            int idx = tid + 512 * j; int m = idx >> 4, cc = idx & 15;
            va[j] = *(const float2*)(A + (size_t)m * lda + kb + 2 * cc);
        }
#pragma unroll
        for (int j = 0; j < 2; ++j) {
            int vidx = tid + 512 * j; int k = vidx >> 5, nv = vidx & 31;
            wb[j] = *(const float4*)(B + (size_t)(kb + k) * ldb + nt * 128 + 4 * nv);
        }
        __syncthreads();
#pragma unroll
        for (int j = 0; j < 3; ++j) {
            int idx = tid + 512 * j; int m = idx >> 4, cc = idx & 15;
            As[(2 * cc) * 98 + m] = va[j].x; As[(2 * cc + 1) * 98 + m] = va[j].y;
        }
#pragma unroll
        for (int j = 0; j < 2; ++j) {
            int vidx = tid + 512 * j; int k = vidx >> 5, nv = vidx & 31;
            *(float4*)&Bs[k * 132 + 4 * nv] = wb[j];
        }
        __syncthreads();
        const int mI = tid >> 5, nI = tid & 31;
#pragma unroll
        for (int k = 0; k < 32; ++k) {
            float2 a01 = *(const float2*)&As[k * 98 + 6 * mI];
            float2 a23 = *(const float2*)&As[k * 98 + 6 * mI + 2];
            float2 a45 = *(const float2*)&As[k * 98 + 6 * mI + 4];
            ulonglong2 bb = *(const ulonglong2*)&Bs[k * 132 + 4 * nI];
            ull ap0 = pk2(a01.x), ap1 = pk2(a01.y), ap2 = pk2(a23.x);
            ull ap3 = pk2(a23.y), ap4 = pk2(a45.x), ap5 = pk2(a45.y);
            ffma2(acc[0][0], ap0, bb.x); ffma2(acc[0][1], ap0, bb.y);
            ffma2(acc[1][0], ap1, bb.x); ffma2(acc[1][1], ap1, bb.y);
            ffma2(acc[2][0], ap2, bb.x); ffma2(acc[2][1], ap2, bb.y);
            ffma2(acc[3][0], ap3, bb.x); ffma2(acc[3][1], ap3, bb.y);
            ffma2(acc[4][0], ap4, bb.x); ffma2(acc[4][1], ap4, bb.y);
            ffma2(acc[5][0], ap5, bb.x); ffma2(acc[5][1], ap5, bb.y);
        }
    }
    const int mI = tid >> 5, nI = tid & 31;
#pragma unroll
    for (int i = 0; i < 6; ++i) {
        int m = 6 * mI + i;
        float2 lo = up2(acc[i][0]), hi = up2(acc[i][1]);
        float4 v = make_float4(lo.x, lo.y, hi.x, hi.y);
        *(float4*)&po[(size_t)m * Nval + 4 * nI] = v;
    }
}

// ---------------- the persistent mega-kernel ----------------
__global__ void __launch_bounds__(TPB, 1)
k_mega(const float* __restrict__ hist, const float* __restrict__ Wl,
       const float* __restrict__ bl, const float* __restrict__ Wr,
       const float* __restrict__ WK, const float* __restrict__ WQ,
       const float* __restrict__ bQ, float* __restrict__ out) {
    __shared__ __align__(16) float As[32 * 98];
    __shared__ __align__(16) float Bs[32 * 132];
    __shared__ unsigned s_base;
    const int gid = blockIdx.x, tid = threadIdx.x;
    const int gtid = gid * TPB + tid;

    if (tid == 0) {
        unsigned b;
        asm volatile("ld.volatile.global.u32 %0, [%1];" : "=r"(b) : "l"(&g_base));
        s_base = b;
    }
    __syncthreads();
    const unsigned base = s_base;

    // ---- phase 0: blocks 0..71 gemm hist0@Wr^T -> g_pU; 72..143 neigh
    if (gid < 72) {
        int nt = gid % 6, ks = gid / 6;
        job_gemmT(hist, LDH, Wr, DD, DD, nt, ks * 64, 2,
                  g_pU + (size_t)ks * PS + nt * 128, As, Bs);
    } else {
        int e0 = (gid - 72) * 1024 + tid;
#pragma unroll
        for (int r = 0; r < 2; ++r) {
            int e = e0 + r * 512;
            int b = e / DD, d = e - b * DD;
            const float* p = hist + (size_t)b * LDH + d;
            float s = 0.f;
#pragma unroll 8
            for (int h = 0; h < BB; ++h) s += p[h * DD];
            g_neigh[e] = s * (1.0f / BB);
        }
    }
    gbar(base + 1 * GRID, 0);

    // ---- phase 1: neigh@Wl^T -> g_pB
    if (gid < 72) {
        int nt = gid % 6, ks = gid / 6;
        job_gemmT(g_neigh, DD, Wl, DD, DD, nt, ks * 64, 2,
                  g_pB + (size_t)ks * PS + nt * 128, As, Bs);
    }
    gbar(base + 2 * GRID, 0);

    // ---- phase 2: bias = sum(pB)+bl; u = sum(pU)+bias
    {
        float sb = 0.f, su = 0.f;
#pragma unroll
        for (int s = 0; s < 12; ++s) {
            sb += g_pB[(size_t)s * PS + gtid];
            su += g_pU[(size_t)s * PS + gtid];
        }
        float bv = sb + bl[gtid % DD];
        g_bias[gtid] = bv;
        g_u[gtid] = su + bv;
    }
    gbar(base + 3 * GRID, 0);

    // ---- phase 3: Q partials: u @ WQ^T (N=256, K=768, kc=32)
    if (gid < 48) {
        int nt = gid % 2, ks = gid / 2;
        job_gemmT(g_u, DD, WQ, DD, AA, nt, ks * 32, 1,
                  g_pQ + (size_t)ks * PSQ + nt * 128, As, Bs);
    }
    gbar(base + 4 * GRID, 0);

    // ---- phase 4: Q = sum(pQ)+bQ
    if (gid < 48) {
        int i = gid * TPB + tid;
        float s = bQ[i % AA];
#pragma unroll
        for (int sl = 0; sl < 24; ++sl) s += g_pQ[(size_t)sl * PSQ + i];
        g_Qv[i] = s;
    }
    gbar(base + 5 * GRID, 0);

    // ---- phase 5: P partials: Q @ WK (NT, N=768, K=256, kc=32)
    if (gid < 48) {
        int nt = gid % 6, ks = gid / 6;
        job_gemmNT(g_Qv, AA, WK, DD, DD, nt, ks * 32, 1,
                   g_pP + (size_t)ks * PS + nt * 128, As, Bs);
    }
    gbar(base + 6 * GRID, 0);

    // ---- phase 6: P = sum(pP)
    {
        float s = 0.f;
#pragma unroll
        for (int sl = 0; sl < 8; ++sl) s += g_pP[(size_t)sl * PS + gtid];
        g_P[gtid] = s;
    }
    gbar(base + 7 * GRID, 0);

    // ---- phase 7: R partials: P @ Wr (NT, N=768, K=768, kc=64)
    if (gid < 72) {
        int nt = gid % 6, ks = gid / 6;
        job_gemmNT(g_P, DD, Wr, DD, DD, nt, ks * 64, 2,
                   g_pR + (size_t)ks * PS + nt * 128, As, Bs);
    }
    gbar(base + 8 * GRID, 0);

    // ---- phase 8: R = sum(pR)
    {
        float s = 0.f;
#pragma unroll
        for (int sl = 0; sl < 12; ++sl) s += g_pR[(size_t)sl * PS + gtid];
        g_R[gtid] = s;
    }
    gbar(base + 9 * GRID, 0);

    // ---- phase 9: attention (96 blocks, 512 threads)
    if (gid < BB) {
        const int b = gid;
        float* Rs = Bs;              // 768 floats
        float* sc = As;              // 104 floats
        float* red = As + 104;       // 2 floats
        const float* hb = hist + (size_t)b * LDH;
        Rs[tid] = g_R[b * DD + tid];
        if (tid < 256) Rs[512 + tid] = g_R[b * DD + 512 + tid];
        __syncthreads();

        int wid = tid >> 5, lane = tid & 31;
        for (int h = wid; h < HH; h += 16) {
            const float* row = hb + h * DD;
            float s = 0.f;
#pragma unroll 6
            for (int d = lane; d < DD; d += 32) s += row[d] * Rs[d];
#pragma unroll
            for (int o = 16; o; o >>= 1) s += __shfl_down_sync(0xffffffffu, s, o);
            if (lane == 0) sc[h] = s * (1.0f / 16.0f);
        }
        __syncthreads();

        if (wid == 0) {
            float v0 = sc[lane];
            float v1 = sc[lane + 32];
            float v2 = sc[lane + 64];
            float v3 = (lane + 96 < HH) ? sc[lane + 96] : -1e30f;
            float m = fmaxf(fmaxf(v0, v1), fmaxf(v2, v3));
#pragma unroll
            for (int o = 16; o; o >>= 1) m = fmaxf(m, __shfl_xor_sync(0xffffffffu, m, o));
            float e = __expf(v0 - m) + __expf(v1 - m) + __expf(v2 - m) +
                      ((lane + 96 < HH) ? __expf(v3 - m) : 0.f);
#pragma unroll
            for (int o = 16; o; o >>= 1) e += __shfl_xor_sync(0xffffffffu, e, o);
            if (lane == 0) { red[0] = m; red[1] = 1.0f / e; }
        }
        __syncthreads();
        if (tid < HH) sc[tid] = __expf(sc[tid] - red[0]) * red[1];
        __syncthreads();

        float s0 = 0.f;
#pragma unroll 4
        for (int h = 0; h < HH; ++h) s0 += sc[h] * hb[h * DD + tid];
        g_hbar[b * DD + tid] = s0;
        if (tid < 256) {
            float s1 = 0.f;
#pragma unroll 4
            for (int h = 0; h < HH; ++h) s1 += sc[h] * hb[h * DD + 512 + tid];
            g_hbar[b * DD + 512 + tid] = s1;
        }
    }
    gbar(base + 10 * GRID, 0);

    // ---- phase 10: out partials: hbar @ Wr^T (kc=64)
    if (gid < 72) {
        int nt = gid % 6, ks = gid / 6;
        job_gemmT(g_hbar, DD, Wr, DD, DD, nt, ks * 64, 2,
                  g_pO + (size_t)ks * PS + nt * 128, As, Bs);
    }
    gbar(base + 11 * GRID, 1);   // final barrier advances g_base

    // ---- phase 11: out = sum(pO) + bias, broadcast over N
    {
        float s = g_bias[gtid];
#pragma unroll
        for (int sl = 0; sl < 12; ++sl) s += g_pO[(size_t)sl * PS + gtid];
        int b = gtid / DD, d = gtid - b * DD;
        float* po = out + (size_t)b * NN * DD + d;
#pragma unroll 8
        for (int n = 0; n < NN; ++n) po[n * DD] = s;
    }
}

// ---------------- launch ---------------------------------------------
extern "C" void kernel_launch(void* const* d_in, const int* in_sizes, int n_in,
                              void* d_out, int out_size) {
    (void)in_sizes; (void)n_in; (void)out_size;
    const float* hist = (const float*)d_in[0];
    const float* Wl = (const float*)d_in[2];
    const float* bl = (const float*)d_in[3];
    const float* Wr = (const float*)d_in[4];
    const float* WK = (const float*)d_in[5];
    const float* WQ = (const float*)d_in[6];
    const float* bQ = (const float*)d_in[7];

    k_mega<<<GRID, TPB>>>(hist, Wl, bl, Wr, WK, WQ, bQ, (float*)d_out);
}